// round 1
// baseline (speedup 1.0000x reference)
#include <cuda_runtime.h>
#include <cuda_bf16.h>
#include <cstdint>

#define HID 4096
#define NTOK 16384
#define NEXP 64
#define TM 128
#define KC 32

// scratch (no allocations allowed) — re-zeroed at the start of every launch
__device__ float g_counts[NEXP];
__device__ float g_sumprobs[NEXP];
__device__ float g_entropy;

__global__ void router_zero() {
    int t = threadIdx.x;
    if (t < NEXP) { g_counts[t] = 0.f; g_sumprobs[t] = 0.f; }
    if (t == 0) g_entropy = 0.f;
}

__global__ __launch_bounds__(256, 1)
void router_main(const float* __restrict__ x, const float* __restrict__ W,
                 float* __restrict__ out) {
    __shared__ float x_s[KC][TM + 1];
    __shared__ float w_s[KC][NEXP + 1];
    __shared__ float logits_s[TM][NEXP + 1];
    __shared__ float invs_s[TM];
    __shared__ float ent_red[256];

    const int tid = threadIdx.x;
    const int t0  = blockIdx.x * TM;
    const int tx  = tid & 15;   // token group
    const int ty  = tid >> 4;   // expert group

    float acc[8][4];
#pragma unroll
    for (int i = 0; i < 8; i++)
#pragma unroll
        for (int j = 0; j < 4; j++) acc[i][j] = 0.f;

    for (int k0 = 0; k0 < HID; k0 += KC) {
        // load x tile [TM x KC] transposed -> x_s[kk][t]
#pragma unroll
        for (int j = 0; j < (TM * KC) / 256; j++) {
            int i  = tid + j * 256;
            int t  = i >> 5;
            int kk = i & 31;
            x_s[kk][t] = x[(size_t)(t0 + t) * HID + k0 + kk];
        }
        // load W tile [NEXP x KC] transposed -> w_s[kk][e]
#pragma unroll
        for (int j = 0; j < (NEXP * KC) / 256; j++) {
            int i  = tid + j * 256;
            int e  = i >> 5;
            int kk = i & 31;
            w_s[kk][e] = W[(size_t)e * HID + k0 + kk];
        }
        __syncthreads();

#pragma unroll
        for (int kk = 0; kk < KC; kk++) {
            float xf[8], wf[4];
#pragma unroll
            for (int i = 0; i < 8; i++) xf[i] = x_s[kk][tx + 16 * i];
#pragma unroll
            for (int j = 0; j < 4; j++) wf[j] = w_s[kk][ty + 16 * j];
#pragma unroll
            for (int i = 0; i < 8; i++)
#pragma unroll
                for (int j = 0; j < 4; j++) acc[i][j] = fmaf(xf[i], wf[j], acc[i][j]);
        }
        __syncthreads();
    }

    // write logits tile to smem
#pragma unroll
    for (int i = 0; i < 8; i++)
#pragma unroll
        for (int j = 0; j < 4; j++)
            logits_s[tx + 16 * i][ty + 16 * j] = acc[i][j];
    __syncthreads();

    // ---- phase A: per-token softmax / top-2 / entropy (threads 0..127) ----
    float ent = 0.f;
    if (tid < TM) {
        const int t = tid;
        float m = -1e30f;
        float v1 = -1e30f, v2 = -1e30f;
        int   i1 = 0, i2 = 0;
#pragma unroll 8
        for (int e = 0; e < NEXP; e++) {
            float l = logits_s[t][e];
            m = fmaxf(m, l);
            if (l > v1)      { v2 = v1; i2 = i1; v1 = l; i1 = e; }
            else if (l > v2) { v2 = l;  i2 = e; }
        }
        float s = 0.f, A = 0.f;
#pragma unroll 8
        for (int e = 0; e < NEXP; e++) {
            float l = logits_s[t][e] - m;
            float p = __expf(l);
            logits_s[t][e] = p;          // stash unnormalized prob for phase B
            s += p;
            A = fmaf(l, p, A);
        }
        invs_s[t] = 1.0f / s;

        float p1 = __expf(v1 - m), p2 = __expf(v2 - m);
        float iw = 1.0f / (p1 + p2);
        int token = t0 + t;
        out[2 * token]                 = (float)i1;
        out[2 * token + 1]             = (float)i2;
        out[2 * NTOK + 2 * token]      = p1 * iw;
        out[2 * NTOK + 2 * token + 1]  = p2 * iw;

        atomicAdd(&g_counts[i1], 1.0f);
        atomicAdd(&g_counts[i2], 1.0f);

        ent = __logf(s) - A / s;       // -sum p log p
    }
    ent_red[tid] = ent;
    __syncthreads();

    for (int off = 128; off > 0; off >>= 1) {
        if (tid < off) ent_red[tid] += ent_red[tid + off];
        __syncthreads();
    }
    if (tid == 0) atomicAdd(&g_entropy, ent_red[0]);

    // ---- phase B: per-expert prob column sums ----
    {
        const int e = tid & 63;
        const int g = tid >> 6;        // 0..3, 32 tokens each
        float ps = 0.f;
#pragma unroll 8
        for (int t = g * 32; t < g * 32 + 32; t++)
            ps = fmaf(logits_s[t][e], invs_s[t], ps);
        atomicAdd(&g_sumprobs[e], ps);
    }
}

__global__ void router_finalize(float* __restrict__ out) {
    int tid = threadIdx.x;
    if (tid < NEXP) {
        out[2 * NTOK * 2 + tid]        = g_counts[tid];
        out[2 * NTOK * 2 + NEXP + tid] = g_sumprobs[tid] * (1.0f / (float)NTOK);
    }
    __syncthreads();
    if (tid == 0) {
        out[2 * NTOK * 2 + 2 * NEXP] = g_entropy * (1.0f / (float)NTOK);
        // gini on sorted counts
        float c[NEXP];
        for (int i = 0; i < NEXP; i++) c[i] = g_counts[i];
        for (int i = 1; i < NEXP; i++) {           // insertion sort ascending
            float v = c[i]; int j = i - 1;
            while (j >= 0 && c[j] > v) { c[j + 1] = c[j]; j--; }
            c[j + 1] = v;
        }
        float num = 0.f, tot = 0.f;
        for (int i = 0; i < NEXP; i++) {
            num = fmaf(2.0f * (float)(i + 1) - (float)NEXP - 1.0f, c[i], num);
            tot += c[i];
        }
        out[2 * NTOK * 2 + 2 * NEXP + 1] = num / ((float)NEXP * tot + 1e-10f);
    }
}

extern "C" void kernel_launch(void* const* d_in, const int* in_sizes, int n_in,
                              void* d_out, int out_size) {
    const float* x = (const float*)d_in[0];
    const float* W = (const float*)d_in[1];
    float* out = (float*)d_out;

    router_zero<<<1, 64>>>();
    router_main<<<NTOK / TM, 256>>>(x, W, out);
    router_finalize<<<1, 64>>>(out);
}

// round 3
// speedup vs baseline: 2.7595x; 2.7595x over previous
#include <cuda_runtime.h>
#include <cstdint>

#define HID 4096
#define NTOK 16384
#define NEXP 64
#define TM 128
#define KC 64
#define NCHUNK (HID / KC)        // 64
#define NCTA (NTOK / TM)         // 128

// ---------------- shared memory layout (bytes, dynamic) ----------------
#define SMEM_TMEM_PTR 0
#define SMEM_MBAR0 16
#define SMEM_MBAR1 24
// tcgen05 path: two 48KB stages of bf16 hi/lo tiles
#define STAGE_BASE 1024
#define XH_OFF 0
#define XL_OFF 16384
#define WH_OFF 32768
#define WL_OFF 40960
#define STAGE_SZ 49152
// fallback path: fp32 tiles
#define FB_X 1024                // [KC][TM+1] fp32 = 33024 B
#define FB_W 34048               // [KC][NEXP+1] fp32 = 16640 B
#define FB_L 50688               // [TM][NEXP+1] fp32 = 33280 B
// common epilogue prob tile (overlaps stage0 / FB_X, used after GEMM done)
#define PN_OFF 1024
#define PN_STRIDE 68             // floats per row (272 B, 16B aligned)
#define SMEM_BYTES (STAGE_BASE + 2 * STAGE_SZ)   // 99328

// idesc kind::f16: dtype=F32(1<<4) atype=BF16(1<<7) btype=BF16(1<<10) N=64(8<<17) M=128(8<<24)
#define IDESC 0x8100490u
// SW128 smem descriptor: layout=SW128(2<<61), version=1(1<<46), SBO=64, LBO=1
#define SMEM_DESC_BASE 0x4000404000010000ull

#if defined(__CUDA_ARCH_FEAT_SM103_ALL) || defined(__CUDA_ARCH_FEAT_SM100_ALL) || defined(__CUDA_ARCH_FEAT_SM101_ALL)
#define TCPATH 1
#else
#define TCPATH 0
#endif

__device__ float g_counts[NEXP];
__device__ float g_sumprobs[NEXP];
__device__ float g_entropy;

static __device__ __forceinline__ uint32_t swz(uint32_t o) { return o ^ ((o >> 3) & 0x70); }

static __device__ __forceinline__ uint32_t s2u(const void* p) {
    uint32_t a;
    asm("{.reg .u64 t; cvta.to.shared.u64 t, %1; cvt.u32.u64 %0, t;}" : "=r"(a) : "l"(p));
    return a;
}

#if TCPATH
static __device__ __forceinline__ uint64_t mk_desc(uint32_t addr) {
    return SMEM_DESC_BASE | (uint64_t)((addr >> 4) & 0x3FFF);
}
static __device__ __forceinline__ void mbar_init(uint32_t mbar, uint32_t cnt) {
    asm volatile("mbarrier.init.shared.b64 [%0], %1;" :: "r"(mbar), "r"(cnt) : "memory");
}
static __device__ __forceinline__ void mbar_wait(uint32_t mbar, uint32_t parity) {
    asm volatile(
        "{.reg .pred P;\n"
        "W_%=:\n"
        "mbarrier.try_wait.parity.acquire.cta.shared::cta.b64 P, [%0], %1, 0x989680;\n"
        "@!P bra W_%=;}\n" :: "r"(mbar), "r"(parity) : "memory");
}
static __device__ __forceinline__ void tmem_alloc(uint32_t smem_dst, uint32_t ncols) {
    asm volatile("tcgen05.alloc.cta_group::1.sync.aligned.shared::cta.b32 [%0], %1;"
                 :: "r"(smem_dst), "r"(ncols) : "memory");
}
static __device__ __forceinline__ void tmem_dealloc(uint32_t tmem, uint32_t ncols) {
    asm volatile("tcgen05.relinquish_alloc_permit.cta_group::1.sync.aligned;");
    asm volatile("tcgen05.dealloc.cta_group::1.sync.aligned.b32 %0, %1;" :: "r"(tmem), "r"(ncols));
}
static __device__ __forceinline__ void mma_f16_ss(uint32_t d, uint64_t a, uint64_t b, uint32_t acc) {
    asm volatile(
        "{.reg .pred p; setp.ne.u32 p, %4, 0;\n"
        "tcgen05.mma.cta_group::1.kind::f16 [%0], %1, %2, %3, {%5,%5,%5,%5}, p;}\n"
        :: "r"(d), "l"(a), "l"(b), "r"(IDESC), "r"(acc), "r"(0u) : "memory");
}
static __device__ __forceinline__ void mma_commit(uint32_t mbar) {
    asm volatile(
        "tcgen05.commit.cta_group::1.mbarrier::arrive::one.shared::cluster.b64 [%0];"
        :: "r"(mbar) : "memory");
}
static __device__ __forceinline__ void ldtm32(uint32_t* r, uint32_t a) {
    asm volatile(
        "tcgen05.ld.sync.aligned.32x32b.x32.b32 "
        "{%0,%1,%2,%3,%4,%5,%6,%7,%8,%9,%10,%11,%12,%13,%14,%15,"
        "%16,%17,%18,%19,%20,%21,%22,%23,%24,%25,%26,%27,%28,%29,%30,%31}, [%32];"
        : "=r"(r[0]), "=r"(r[1]), "=r"(r[2]), "=r"(r[3]), "=r"(r[4]), "=r"(r[5]),
          "=r"(r[6]), "=r"(r[7]), "=r"(r[8]), "=r"(r[9]), "=r"(r[10]), "=r"(r[11]),
          "=r"(r[12]), "=r"(r[13]), "=r"(r[14]), "=r"(r[15]), "=r"(r[16]), "=r"(r[17]),
          "=r"(r[18]), "=r"(r[19]), "=r"(r[20]), "=r"(r[21]), "=r"(r[22]), "=r"(r[23]),
          "=r"(r[24]), "=r"(r[25]), "=r"(r[26]), "=r"(r[27]), "=r"(r[28]), "=r"(r[29]),
          "=r"(r[30]), "=r"(r[31])
        : "r"(a));
}
// pack 4 fp32 -> bf16 hi pair + bf16 lo pair, store swizzled
static __device__ __forceinline__ void cvt_store(char* sm, uint32_t stage_base,
                                                 uint32_t hi_off, uint32_t lo_off,
                                                 int row, int qb, float4 v) {
    uint32_t h0, h1, l0, l1;
    asm("cvt.rn.bf16x2.f32 %0, %1, %2;" : "=r"(h0) : "f"(v.y), "f"(v.x));
    asm("cvt.rn.bf16x2.f32 %0, %1, %2;" : "=r"(h1) : "f"(v.w), "f"(v.z));
    float fx = __uint_as_float(h0 << 16);
    float fy = __uint_as_float(h0 & 0xffff0000u);
    float fz = __uint_as_float(h1 << 16);
    float fw = __uint_as_float(h1 & 0xffff0000u);
    asm("cvt.rn.bf16x2.f32 %0, %1, %2;" : "=r"(l0) : "f"(v.y - fy), "f"(v.x - fx));
    asm("cvt.rn.bf16x2.f32 %0, %1, %2;" : "=r"(l1) : "f"(v.w - fw), "f"(v.z - fz));
    uint32_t off = swz((uint32_t)(row * 128 + qb));
    *(uint2*)(sm + stage_base + hi_off + off) = make_uint2(h0, h1);
    *(uint2*)(sm + stage_base + lo_off + off) = make_uint2(l0, l1);
}
#endif  // TCPATH

__global__ void router_zero() {
    int t = threadIdx.x;
    if (t < NEXP) { g_counts[t] = 0.f; g_sumprobs[t] = 0.f; }
    if (t == 0) g_entropy = 0.f;
}

__global__ __launch_bounds__(256, 1)
void router_main(const float* __restrict__ x, const float* __restrict__ W,
                 float* __restrict__ out) {
    extern __shared__ char sm[];
    const uint32_t smb = s2u(sm);
    const int tid = threadIdx.x;
    const int lane = tid & 31;
    const int t0 = blockIdx.x * TM;

    // loader indexing shared by both paths:
    const int q  = tid & 15;      // k-quad within chunk (4 fp32)
    const int tb = tid >> 4;      // row base (0..15)
    const float* xp = x + (size_t)(t0 + tb) * HID + q * 4;
    const float* wp = W + (size_t)tb * HID + q * 4;

    float l[64];                  // this thread's token logits (tid < 128)

#if TCPATH
    // ======================= tcgen05 path =======================
    const int wid = tid >> 5;
    if (tid == 0) { mbar_init(smb + SMEM_MBAR0, 1); mbar_init(smb + SMEM_MBAR1, 1); }
    if (wid == 0) tmem_alloc(smb + SMEM_TMEM_PTR, 64);
    __syncthreads();
    uint32_t tmem;
    asm volatile("ld.shared.b32 %0, [%1];" : "=r"(tmem) : "r"(smb + SMEM_TMEM_PTR));

    float4 xr[8], wr[4];
#pragma unroll
    for (int r = 0; r < 8; r++) xr[r] = *(const float4*)(xp + (size_t)r * 16 * HID);
#pragma unroll
    for (int p = 0; p < 4; p++) wr[p] = *(const float4*)(wp + (size_t)p * 16 * HID);

    int ph0 = 0, ph1 = 0;
    const int qb = q * 8;

#pragma unroll 1
    for (int c = 0; c < NCHUNK; c++) {
        const uint32_t st = STAGE_BASE + (c & 1) * STAGE_SZ;
        if (c >= 2) {
            if (c & 1) { mbar_wait(smb + SMEM_MBAR1, ph1); ph1 ^= 1; }
            else       { mbar_wait(smb + SMEM_MBAR0, ph0); ph0 ^= 1; }
        }
#pragma unroll
        for (int r = 0; r < 8; r++) cvt_store(sm, st, XH_OFF, XL_OFF, tb + r * 16, qb, xr[r]);
#pragma unroll
        for (int p = 0; p < 4; p++) cvt_store(sm, st, WH_OFF, WL_OFF, tb + p * 16, qb, wr[p]);

        if (c + 1 < NCHUNK) {
            const int k0 = (c + 1) * KC;
#pragma unroll
            for (int r = 0; r < 8; r++) xr[r] = *(const float4*)(xp + k0 + (size_t)r * 16 * HID);
#pragma unroll
            for (int p = 0; p < 4; p++) wr[p] = *(const float4*)(wp + k0 + (size_t)p * 16 * HID);
        }
        __syncthreads();

        if (tid == 0) {
            asm volatile("fence.proxy.async.shared::cta;" ::: "memory");
            uint64_t axh = mk_desc(smb + st + XH_OFF);
            uint64_t axl = mk_desc(smb + st + XL_OFF);
            uint64_t bwh = mk_desc(smb + st + WH_OFF);
            uint64_t bwl = mk_desc(smb + st + WL_OFF);
#pragma unroll
            for (int k = 0; k < 4; k++) mma_f16_ss(tmem, axh + 2 * k, bwh + 2 * k, (c > 0) | k);
#pragma unroll
            for (int k = 0; k < 4; k++) mma_f16_ss(tmem, axh + 2 * k, bwl + 2 * k, 1);
#pragma unroll
            for (int k = 0; k < 4; k++) mma_f16_ss(tmem, axl + 2 * k, bwh + 2 * k, 1);
#pragma unroll
            for (int k = 0; k < 4; k++) mma_f16_ss(tmem, axl + 2 * k, bwl + 2 * k, 1);
            mma_commit(smb + ((c & 1) ? SMEM_MBAR1 : SMEM_MBAR0));
        }
    }
    // last two commits still pending (chunks 62 -> mbar0, 63 -> mbar1)
    mbar_wait(smb + SMEM_MBAR0, ph0);
    mbar_wait(smb + SMEM_MBAR1, ph1);
    asm volatile("tcgen05.fence::after_thread_sync;" ::: "memory");

    if (tid < 128) {              // warps 0-3: lane reads row = tid of D
        ldtm32((uint32_t*)l, tmem);
        ldtm32((uint32_t*)l + 32, tmem + 32);
        asm volatile("tcgen05.wait::ld.sync.aligned;" ::: "memory");
    }
#else
    // ======================= fp32 SIMT fallback =======================
    float* x_s = (float*)(sm + FB_X);     // [KC][TM+1]
    float* w_s = (float*)(sm + FB_W);     // [KC][NEXP+1]
    float* l_s = (float*)(sm + FB_L);     // [TM][NEXP+1]
    const int tx = tid & 15;
    const int ty = tid >> 4;

    float acc[8][4];
#pragma unroll
    for (int i = 0; i < 8; i++)
#pragma unroll
        for (int j = 0; j < 4; j++) acc[i][j] = 0.f;

    float4 xr[8], wr[4];
#pragma unroll
    for (int r = 0; r < 8; r++) xr[r] = *(const float4*)(xp + (size_t)r * 16 * HID);
#pragma unroll
    for (int p = 0; p < 4; p++) wr[p] = *(const float4*)(wp + (size_t)p * 16 * HID);

#pragma unroll 1
    for (int c = 0; c < NCHUNK; c++) {
        // store current chunk (transposed) to smem
#pragma unroll
        for (int r = 0; r < 8; r++) {
            const float v[4] = {xr[r].x, xr[r].y, xr[r].z, xr[r].w};
#pragma unroll
            for (int j = 0; j < 4; j++) x_s[(q * 4 + j) * (TM + 1) + tb + 16 * r] = v[j];
        }
#pragma unroll
        for (int p = 0; p < 4; p++) {
            const float v[4] = {wr[p].x, wr[p].y, wr[p].z, wr[p].w};
#pragma unroll
            for (int j = 0; j < 4; j++) w_s[(q * 4 + j) * (NEXP + 1) + tb + 16 * p] = v[j];
        }
        __syncthreads();

        // prefetch next chunk into registers (overlaps compute below)
        if (c + 1 < NCHUNK) {
            const int k0 = (c + 1) * KC;
#pragma unroll
            for (int r = 0; r < 8; r++) xr[r] = *(const float4*)(xp + k0 + (size_t)r * 16 * HID);
#pragma unroll
            for (int p = 0; p < 4; p++) wr[p] = *(const float4*)(wp + k0 + (size_t)p * 16 * HID);
        }

#pragma unroll 8
        for (int kk = 0; kk < KC; kk++) {
            float xf[8], wf[4];
#pragma unroll
            for (int i = 0; i < 8; i++) xf[i] = x_s[kk * (TM + 1) + tx + 16 * i];
#pragma unroll
            for (int j = 0; j < 4; j++) wf[j] = w_s[kk * (NEXP + 1) + ty + 16 * j];
#pragma unroll
            for (int i = 0; i < 8; i++)
#pragma unroll
                for (int j = 0; j < 4; j++) acc[i][j] = fmaf(xf[i], wf[j], acc[i][j]);
        }
        __syncthreads();
    }
#pragma unroll
    for (int i = 0; i < 8; i++)
#pragma unroll
        for (int j = 0; j < 4; j++)
            l_s[(tx + 16 * i) * (NEXP + 1) + ty + 16 * j] = acc[i][j];
    __syncthreads();
    if (tid < 128) {
#pragma unroll
        for (int e = 0; e < NEXP; e++) l[e] = l_s[tid * (NEXP + 1) + e];
    }
#endif

    // ======================= common epilogue =======================
    if (tid < 128) {
        float m = -1e30f, v1 = -1e30f, v2 = -1e30f;
        int i1 = 0, i2 = 0;
#pragma unroll
        for (int e = 0; e < NEXP; e++) {
            float v = l[e];
            m = fmaxf(m, v);
            if (v > v1)      { v2 = v1; i2 = i1; v1 = v; i1 = e; }
            else if (v > v2) { v2 = v;  i2 = e; }
        }
        float s = 0.f, A = 0.f;
#pragma unroll
        for (int e = 0; e < NEXP; e++) {
            float d = l[e] - m;
            float p = __expf(d);
            l[e] = p;
            s += p;
            A = fmaf(d, p, A);
        }
        const float inv = 1.0f / s;

        const float p1 = __expf(v1 - m), p2 = __expf(v2 - m);
        const float iw = 1.0f / (p1 + p2);
        const int token = t0 + tid;
        out[2 * token]                = (float)i1;
        out[2 * token + 1]            = (float)i2;
        out[2 * NTOK + 2 * token]     = p1 * iw;
        out[2 * NTOK + 2 * token + 1] = p2 * iw;
        atomicAdd(&g_counts[i1], 1.0f);
        atomicAdd(&g_counts[i2], 1.0f);

        float ent = __logf(s) - A * inv;
#pragma unroll
        for (int o = 16; o > 0; o >>= 1) ent += __shfl_xor_sync(0xffffffffu, ent, o);
        if (lane == 0) atomicAdd(&g_entropy, ent);

        float* pn = (float*)(sm + PN_OFF) + tid * PN_STRIDE;
#pragma unroll
        for (int e4 = 0; e4 < 16; e4++) {
            float4 v;
            v.x = l[4 * e4 + 0] * inv;
            v.y = l[4 * e4 + 1] * inv;
            v.z = l[4 * e4 + 2] * inv;
            v.w = l[4 * e4 + 3] * inv;
            *(float4*)(pn + 4 * e4) = v;
        }
    }
    __syncthreads();

    // per-expert prob column sums over the CTA's 128 tokens
    {
        const int e = tid & 63;
        const int g = tid >> 6;
        const float* pn = (float*)(sm + PN_OFF);
        float ps = 0.f;
#pragma unroll 8
        for (int t = g * 32; t < g * 32 + 32; t++)
            ps += pn[t * PN_STRIDE + e];
        atomicAdd(&g_sumprobs[e], ps);
    }
#if TCPATH
    __syncthreads();
    if ((tid >> 5) == 0) tmem_dealloc(tmem, 64);
#endif
}

__global__ void router_finalize(float* __restrict__ out) {
    int tid = threadIdx.x;
    if (tid < NEXP) {
        out[2 * NTOK * 2 + tid]        = g_counts[tid];
        out[2 * NTOK * 2 + NEXP + tid] = g_sumprobs[tid] * (1.0f / (float)NTOK);
    }
    __syncthreads();
    if (tid == 0) {
        out[2 * NTOK * 2 + 2 * NEXP] = g_entropy * (1.0f / (float)NTOK);
        float c[NEXP];
        for (int i = 0; i < NEXP; i++) c[i] = g_counts[i];
        for (int i = 1; i < NEXP; i++) {
            float v = c[i]; int j = i - 1;
            while (j >= 0 && c[j] > v) { c[j + 1] = c[j]; j--; }
            c[j + 1] = v;
        }
        float num = 0.f, tot = 0.f;
        for (int i = 0; i < NEXP; i++) {
            num = fmaf(2.0f * (float)(i + 1) - (float)NEXP - 1.0f, c[i], num);
            tot += c[i];
        }
        out[2 * NTOK * 2 + 2 * NEXP + 1] = num / ((float)NEXP * tot + 1e-10f);
    }
}

extern "C" void kernel_launch(void* const* d_in, const int* in_sizes, int n_in,
                              void* d_out, int out_size) {
    const float* x = (const float*)d_in[0];
    const float* W = (const float*)d_in[1];
    float* out = (float*)d_out;

    cudaFuncSetAttribute(router_main, cudaFuncAttributeMaxDynamicSharedMemorySize, SMEM_BYTES);

    router_zero<<<1, 64>>>();
    router_main<<<NCTA, 256, SMEM_BYTES>>>(x, W, out);
    router_finalize<<<1, 64>>>(out);
}